// round 1
// baseline (speedup 1.0000x reference)
#include <cuda_runtime.h>
#include <stdint.h>

// xxh32 primes
#define P2 2246822519u
#define P3 3266489917u
#define P4 668265263u
#define P5 374761393u

__device__ __forceinline__ uint32_t rotl32(uint32_t v, int r) {
    return (v << r) | (v >> (32 - r));
}

__device__ __forceinline__ uint32_t xxh32_4(uint32_t val, uint32_t seed) {
    uint32_t acc = seed + P5 + 4u;
    acc = acc + val * P3;
    acc = rotl32(acc, 17) * P4;
    acc ^= acc >> 15;
    acc *= P2;
    acc ^= acc >> 13;
    acc *= P3;
    acc ^= acc >> 16;
    return acc;
}

// One 16-thread group per (i, j) pair. Each thread computes the hash
// (cheap, redundant across the group) and moves one float4 (16 B) of the
// 64-float embedding row: 256 B contiguous load + 256 B contiguous store.
__global__ void unified_embedding_kernel(
    const int* __restrict__ x,      // [N]
    const int* __restrict__ fnum,   // [F]
    const float4* __restrict__ emb, // [levels, 16] as float4
    float4* __restrict__ out,       // [N*F, 16] as float4
    int N, int F, uint32_t levels)
{
    uint32_t tid = blockIdx.x * blockDim.x + threadIdx.x;
    uint32_t pair = tid >> 4;
    uint32_t lane = tid & 15u;
    uint32_t total = (uint32_t)N * (uint32_t)F;
    if (pair >= total) return;

    uint32_t i = pair / (uint32_t)F;
    uint32_t j = pair - i * (uint32_t)F;

    uint32_t val  = (uint32_t)__ldg(&x[i]);
    uint32_t seed = (uint32_t)__ldg(&fnum[j]);

    uint32_t h = xxh32_4(val, seed);
    uint32_t idx = h % levels;

    out[(size_t)pair * 16 + lane] = __ldg(&emb[(size_t)idx * 16 + lane]);
}

extern "C" void kernel_launch(void* const* d_in, const int* in_sizes, int n_in,
                              void* d_out, int out_size) {
    const int*    x    = (const int*)d_in[0];
    const int*    fnum = (const int*)d_in[1];
    const float4* emb  = (const float4*)d_in[2];
    float4*       out  = (float4*)d_out;

    int N = in_sizes[0];
    int F = in_sizes[1];
    uint32_t levels = (uint32_t)(in_sizes[2] / 64);  // EMB_DIM = 64

    long long total_threads = (long long)N * F * 16;
    int block = 256;
    int grid = (int)((total_threads + block - 1) / block);

    unified_embedding_kernel<<<grid, block>>>(x, fnum, emb, out, N, F, levels);
}

// round 2
// speedup vs baseline: 1.2685x; 1.2685x over previous
#include <cuda_runtime.h>
#include <stdint.h>

// xxh32 primes
#define P2 2246822519u
#define P3 3266489917u
#define P4 668265263u
#define P5 374761393u

__device__ __forceinline__ uint32_t rotl32(uint32_t v, int r) {
    return (v << r) | (v >> (32 - r));
}

__device__ __forceinline__ uint32_t xxh32_4(uint32_t val, uint32_t seed) {
    uint32_t acc = seed + P5 + 4u;
    acc = acc + val * P3;
    acc = rotl32(acc, 17) * P4;
    acc ^= acc >> 15;
    acc *= P2;
    acc ^= acc >> 13;
    acc *= P3;
    acc ^= acc >> 16;
    return acc;
}

#define UNROLL 4

// One 16-thread group per UNROLL consecutive (i, j) pairs.
// Each thread issues UNROLL independent float4 gathers (4x MLP vs R1),
// then UNROLL streaming stores (evict-first, keep L2 for the emb table).
__global__ void unified_embedding_kernel(
    const int* __restrict__ x,      // [N]
    const int* __restrict__ fnum,   // [F]
    const float4* __restrict__ emb, // [levels, 16] as float4
    float4* __restrict__ out,       // [N*F, 16] as float4
    int N, int F, uint32_t levels)
{
    uint32_t gid  = blockIdx.x * (blockDim.x >> 4) + (threadIdx.x >> 4);
    uint32_t lane = threadIdx.x & 15u;
    uint32_t total = (uint32_t)N * (uint32_t)F;
    uint32_t pair0 = gid * UNROLL;
    if (pair0 >= total) return;

    // Compute indices for all UNROLL pairs first (independent ALU work)
    size_t src_off[UNROLL];
    #pragma unroll
    for (int k = 0; k < UNROLL; k++) {
        uint32_t pair = pair0 + k;
        uint32_t i = pair / (uint32_t)F;
        uint32_t j = pair - i * (uint32_t)F;
        uint32_t val  = (uint32_t)__ldg(&x[i]);
        uint32_t seed = (uint32_t)__ldg(&fnum[j]);
        uint32_t idx = xxh32_4(val, seed) % levels;
        src_off[k] = (size_t)idx * 16 + lane;
    }

    // Issue all gathers back-to-back: 4 outstanding loads per thread
    float4 v[UNROLL];
    #pragma unroll
    for (int k = 0; k < UNROLL; k++) {
        v[k] = __ldg(&emb[src_off[k]]);
    }

    // Streaming stores: output is never re-read, don't pollute L2
    #pragma unroll
    for (int k = 0; k < UNROLL; k++) {
        __stcs(&out[(size_t)(pair0 + k) * 16 + lane], v[k]);
    }
}

extern "C" void kernel_launch(void* const* d_in, const int* in_sizes, int n_in,
                              void* d_out, int out_size) {
    const int*    x    = (const int*)d_in[0];
    const int*    fnum = (const int*)d_in[1];
    const float4* emb  = (const float4*)d_in[2];
    float4*       out  = (float4*)d_out;

    int N = in_sizes[0];
    int F = in_sizes[1];
    uint32_t levels = (uint32_t)(in_sizes[2] / 64);  // EMB_DIM = 64

    long long total_pairs = (long long)N * F;
    long long groups = (total_pairs + UNROLL - 1) / UNROLL;
    int block = 256;
    int groups_per_block = block / 16;
    int grid = (int)((groups + groups_per_block - 1) / groups_per_block);

    unified_embedding_kernel<<<grid, block>>>(x, fnum, emb, out, N, F, levels);
}

// round 3
// speedup vs baseline: 1.3054x; 1.0291x over previous
#include <cuda_runtime.h>
#include <stdint.h>

// xxh32 primes
#define P2 2246822519u
#define P3 3266489917u
#define P4 668265263u
#define P5 374761393u

__device__ __forceinline__ uint32_t rotl32(uint32_t v, int r) {
    return (v << r) | (v >> (32 - r));
}

__device__ __forceinline__ uint32_t xxh32_4(uint32_t val, uint32_t seed) {
    uint32_t acc = seed + P5 + 4u;
    acc = acc + val * P3;
    acc = rotl32(acc, 17) * P4;
    acc ^= acc >> 15;
    acc *= P2;
    acc ^= acc >> 13;
    acc *= P3;
    acc ^= acc >> 16;
    return acc;
}

#define PAIRS_PER_WARP 16

// One warp handles 16 consecutive (i,j) pairs.
//  - each lane computes ONE hash (pair0 + lane%16; both half-warps compute the
//    same 16 so shfl width=16 works), killing the 16x-redundant ALU work
//  - each lane then issues 8 independent float4 gathers (high MLP) covering
//    2 pairs' 256B rows per round (512B coalesced per warp)
//  - 8 streaming stores (output never re-read; keep L2 for the emb table,
//    whose ~70MB hot working set fits in the 126MB L2)
__global__ void unified_embedding_kernel(
    const int* __restrict__ x,      // [N]
    const int* __restrict__ fnum,   // [F]
    const float4* __restrict__ emb, // [levels, 16] as float4
    float4* __restrict__ out,       // [N*F, 16] as float4
    int N, int F, uint32_t levels)
{
    uint32_t warp_id = (blockIdx.x * blockDim.x + threadIdx.x) >> 5;
    uint32_t lane    = threadIdx.x & 31u;
    uint32_t lane16  = lane & 15u;
    uint32_t half    = lane >> 4;          // 0 or 1

    uint32_t total = (uint32_t)N * (uint32_t)F;
    uint32_t pair0 = warp_id * PAIRS_PER_WARP;
    if (pair0 >= total) return;

    // Each lane hashes one pair (duplicated across the two half-warps)
    uint32_t my_pair = pair0 + lane16;
    uint32_t i = my_pair / (uint32_t)F;
    uint32_t j = my_pair - i * (uint32_t)F;
    uint32_t val  = (uint32_t)__ldg(&x[i]);
    uint32_t seed = (uint32_t)__ldg(&fnum[j]);
    uint32_t my_idx = xxh32_4(val, seed) % levels;

    // Gather: round k loads pairs (pair0 + 2k) and (pair0 + 2k + 1):
    // half-warp 0 -> pair 2k, half-warp 1 -> pair 2k+1. 8 independent loads.
    float4 v[8];
    #pragma unroll
    for (int k = 0; k < 8; k++) {
        uint32_t src_lane = 2u * k + half;   // within width-16 group
        uint32_t idx = __shfl_sync(0xffffffffu, my_idx, src_lane, 16);
        v[k] = __ldg(&emb[(size_t)idx * 16 + lane16]);
    }

    // Coalesced streaming stores: round k writes 512B at pair (pair0+2k)
    #pragma unroll
    for (int k = 0; k < 8; k++) {
        uint32_t pair = pair0 + 2u * k + half;
        __stcs(&out[(size_t)pair * 16 + lane16], v[k]);
    }
}

extern "C" void kernel_launch(void* const* d_in, const int* in_sizes, int n_in,
                              void* d_out, int out_size) {
    const int*    x    = (const int*)d_in[0];
    const int*    fnum = (const int*)d_in[1];
    const float4* emb  = (const float4*)d_in[2];
    float4*       out  = (float4*)d_out;

    int N = in_sizes[0];
    int F = in_sizes[1];
    uint32_t levels = (uint32_t)(in_sizes[2] / 64);  // EMB_DIM = 64

    long long total_pairs = (long long)N * F;
    long long warps = (total_pairs + PAIRS_PER_WARP - 1) / PAIRS_PER_WARP;
    int block = 256;
    int warps_per_block = block / 32;
    int grid = (int)((warps + warps_per_block - 1) / warps_per_block);

    unified_embedding_kernel<<<grid, block>>>(x, fnum, emb, out, N, F, levels);
}